// round 9
// baseline (speedup 1.0000x reference)
#include <cuda_runtime.h>
#include <cstdint>

// AttentionOutput: causal complex leaky-relu attention + linear head.
// B=4, N=4096, F=64.  mma.sync.m16n8k8.tf32; 128-row KV tiles; pair-balanced CTAs.

#define NT 256
#define STR 68      // stride (floats) for Q/K/Watt
#define VSTR 72     // stride for V
#define WSTR 132    // stride for attention-weight tile W (64 x 128)
// smem offsets in floats
#define QR 0                    // 64 x 68
#define QI 4352
#define KR 8704                 // 128 x 68
#define KI 17408
#define VR 26112                // 128 x 72
#define VI 35328
#define SMF 44544
#define SMB (SMF * 4)           // 178176 bytes
#define WR KR                   // W aliases K (64 x 132 = 8448 <= 8704)
#define WI KI
#define WATT KR                 // linear head reuses K region
#define BIAS KI

__device__ __forceinline__ float rna(float x) {
    uint32_t u;
    asm("cvt.rna.tf32.f32 %0, %1;" : "=r"(u) : "f"(x));
    return __uint_as_float(u);
}

__device__ __forceinline__ void mma8(float* c, float a0, float a1, float a2, float a3,
                                     float b0, float b1) {
    uint32_t A0 = __float_as_uint(a0), A1 = __float_as_uint(a1);
    uint32_t A2 = __float_as_uint(a2), A3 = __float_as_uint(a3);
    uint32_t B0 = __float_as_uint(b0), B1 = __float_as_uint(b1);
    asm volatile("mma.sync.aligned.m16n8k8.row.col.f32.tf32.tf32.f32 "
                 "{%0,%1,%2,%3},{%4,%5,%6,%7},{%8,%9},{%0,%1,%2,%3};"
                 : "+f"(c[0]), "+f"(c[1]), "+f"(c[2]), "+f"(c[3])
                 : "r"(A0), "r"(A1), "r"(A2), "r"(A3), "r"(B0), "r"(B1));
}

#define LDQUADS(arr, base, stride, v0, v1, v2, v3)                          \
    float v0 = sm[(arr) + (base)];                                          \
    float v1 = sm[(arr) + (base) + 8 * (stride)];                           \
    float v2 = sm[(arr) + (base) + 4];                                      \
    float v3 = sm[(arr) + (base) + 8 * (stride) + 4];

#define SPLIT4(x0, x1, x2, x3, h0, h1, h2, h3, l0, l1, l2, l3)              \
    float h0 = rna(x0), h1 = rna(x1), h2 = rna(x2), h3 = rna(x3);           \
    float l0 = x0 - h0, l1 = x1 - h1, l2 = x2 - h2, l3 = x3 - h3;

__global__ __launch_bounds__(NT)
void attn_k(const float2* __restrict__ Qg, const float2* __restrict__ Kg,
            const float2* __restrict__ Vg, const float* __restrict__ Wg,
            const float* __restrict__ bg, float2* __restrict__ Og)
{
    extern __shared__ float sm[];
    const int tid = threadIdx.x, w = tid >> 5, l = tid & 31;
    const int g = l >> 2, t = l & 3;
    const int b = blockIdx.y;
    const int N = 4096;

    const int i0w = (w >> 1) * 16, j0w = (w & 1) * 64;     // phase-1: warp tile 16x64
    const int i0p = (w & 3) * 16, f0p = (w >> 2) * 32;     // phase-2: warp tile 16x32
    const float scale = 1.0f / 64.0f;                      // 1/sqrt(4096)

    // complementary pair: (bx+1) + (64-bx) = 65 qtile-units -> 33 KV128 tiles, all equal
    #pragma unroll 1
    for (int pi = 0; pi < 2; ++pi) {
        const int qt = pi ? (63 - (int)blockIdx.x) : (int)blockIdx.x;
        const int qi0 = qt * 64;

        __syncthreads();   // previous iteration's smem reads complete

        // ---- load Q tile (pre-rounded tf32) ----
        {
            const float2* Qp = Qg + ((size_t)b * N + qi0) * 64;
            for (int idx = tid; idx < 64 * 64; idx += NT) {
                float2 q = Qp[idx];
                int a = (idx >> 6) * STR + (idx & 63);
                sm[QR + a] = rna(q.x); sm[QI + a] = rna(q.y);
            }
        }

        float o_r[4][4], o_i[4][4];
        #pragma unroll
        for (int nb = 0; nb < 4; ++nb)
            #pragma unroll
            for (int r = 0; r < 4; ++r) { o_r[nb][r] = 0.f; o_i[nb][r] = 0.f; }

        const int nkt = (qt >> 1) + 1;   // ceil((qt+1)/2) 128-row KV tiles
        for (int tt = 0; tt < nkt; ++tt) {
            const int kt = tt * 128;
            __syncthreads();   // prior phase-2 V/W reads done (also makes Q visible)

            // ---- load K, V: 128 rows (pre-rounded tf32) ----
            {
                const float2* Kp = Kg + ((size_t)b * N + kt) * 64;
                const float2* Vp = Vg + ((size_t)b * N + kt) * 64;
                #pragma unroll 4
                for (int idx = tid; idx < 128 * 64; idx += NT) {
                    float2 kv = Kp[idx];
                    float2 vv = Vp[idx];
                    int j = idx >> 6, f = idx & 63;
                    sm[KR + j * STR + f] = rna(kv.x);
                    sm[KI + j * STR + f] = rna(kv.y);
                    sm[VR + j * VSTR + f] = rna(vv.x);
                    sm[VI + j * VSTR + f] = rna(vv.y);
                }
            }
            __syncthreads();

            // ---- phase 1: crr = QrKr, cii = QiKi, csi = QrKi + QiKr  (64x128) ----
            float crr[8][4], cii[8][4], csi[8][4];
            #pragma unroll
            for (int nb = 0; nb < 8; ++nb)
                #pragma unroll
                for (int r = 0; r < 4; ++r) { crr[nb][r] = 0.f; cii[nb][r] = 0.f; csi[nb][r] = 0.f; }

            for (int kk = 0; kk < 8; ++kk) {
                const int k0 = kk * 8;
                const int ab = (i0w + g) * STR + k0 + t;
                LDQUADS(QR, ab, STR, qr0, qr1, qr2, qr3)
                LDQUADS(QI, ab, STR, qi0_, qi1, qi2, qi3)
                #pragma unroll
                for (int nb = 0; nb < 8; ++nb) {
                    const int bb = (j0w + nb * 8 + g) * STR + k0 + t;
                    float kr0 = sm[KR + bb], kr1 = sm[KR + bb + 4];
                    float ki0 = sm[KI + bb], ki1 = sm[KI + bb + 4];
                    mma8(crr[nb], qr0, qr1, qr2, qr3, kr0, kr1);
                    mma8(cii[nb], qi0_, qi1, qi2, qi3, ki0, ki1);
                    mma8(csi[nb], qr0, qr1, qr2, qr3, ki0, ki1);
                    mma8(csi[nb], qi0_, qi1, qi2, qi3, kr0, kr1);
                }
            }
            __syncthreads();   // phase-1 K reads done before W overwrites K region

            // ---- epilogue: scale + leaky + causal mask -> W (tf32, aliased on K) ----
            #pragma unroll
            for (int nb = 0; nb < 8; ++nb) {
                float vr_[4], vi_[4];
                #pragma unroll
                for (int r = 0; r < 4; ++r) {
                    int il = i0w + g + ((r & 2) ? 8 : 0);
                    int jg = kt + j0w + nb * 8 + 2 * t + (r & 1);
                    float sr = (crr[nb][r] - cii[nb][r]) * scale;
                    float si = csi[nb][r] * scale;
                    sr = sr >= 0.f ? sr : 0.01f * sr;
                    si = si >= 0.f ? si : 0.01f * si;
                    if (jg > qi0 + il) { sr = 0.f; si = 0.f; }
                    vr_[r] = rna(sr); vi_[r] = rna(si);
                }
                int wb = (i0w + g) * WSTR + j0w + nb * 8 + 2 * t;
                *(float2*)&sm[WR + wb]            = make_float2(vr_[0], vr_[1]);
                *(float2*)&sm[WR + wb + 8 * WSTR] = make_float2(vr_[2], vr_[3]);
                *(float2*)&sm[WI + wb]            = make_float2(vi_[0], vi_[1]);
                *(float2*)&sm[WI + wb + 8 * WSTR] = make_float2(vi_[2], vi_[3]);
            }
            __syncthreads();

            // ---- phase 2: O += W V over 128-row k-dim (single-pass tf32) ----
            for (int kk = 0; kk < 16; ++kk) {
                const int k0 = kk * 8;
                const int ab = (i0p + g) * WSTR + k0 + t;
                LDQUADS(WR, ab, WSTR, wr0, wr1, wr2, wr3)
                LDQUADS(WI, ab, WSTR, wi0, wi1, wi2, wi3)
                #pragma unroll
                for (int nb = 0; nb < 4; ++nb) {
                    const int vb = (k0 + t) * VSTR + f0p + nb * 8 + g;
                    float v0 = sm[VR + vb], v1 = sm[VR + vb + 4 * VSTR];
                    float u0 = sm[VI + vb], u1 = sm[VI + vb + 4 * VSTR];
                    mma8(o_r[nb], wr0, wr1, wr2, wr3, v0, v1);
                    mma8(o_i[nb], wi0, wi1, wi2, wi3, u0, u1);
                }
            }
        }

        // ---- linear head via mma: out = O @ Watt^T + b ----
        __syncthreads();   // all phase-2 done before overwriting Q/K regions
        #pragma unroll
        for (int nb = 0; nb < 4; ++nb)
            #pragma unroll
            for (int r = 0; r < 4; ++r) {
                int il = i0p + g + ((r & 2) ? 8 : 0);
                int fo = f0p + nb * 8 + 2 * t + (r & 1);
                sm[QR + il * STR + fo] = o_r[nb][r];
                sm[QI + il * STR + fo] = o_i[nb][r];
            }
        for (int idx = tid; idx < 64 * 64; idx += NT)
            sm[WATT + (idx >> 6) * STR + (idx & 63)] = Wg[idx];
        if (tid < 64) sm[BIAS + tid] = bg[tid];
        __syncthreads();

        float hr[4][4], hi_[4][4];
        #pragma unroll
        for (int nb = 0; nb < 4; ++nb)
            #pragma unroll
            for (int r = 0; r < 4; ++r) { hr[nb][r] = 0.f; hi_[nb][r] = 0.f; }

        for (int kk = 0; kk < 8; ++kk) {
            const int k0 = kk * 8;
            const int ab = (i0p + g) * STR + k0 + t;
            LDQUADS(QR, ab, STR, pr0, pr1, pr2, pr3)
            LDQUADS(QI, ab, STR, pi0, pi1, pi2, pi3)
            SPLIT4(pr0, pr1, pr2, pr3, orh0, orh1, orh2, orh3, orl0, orl1, orl2, orl3)
            SPLIT4(pi0, pi1, pi2, pi3, oih0, oih1, oih2, oih3, oil0, oil1, oil2, oil3)
            #pragma unroll
            for (int nb = 0; nb < 4; ++nb) {
                const int wb2 = (f0p + nb * 8 + g) * STR + k0 + t;
                float w0 = sm[WATT + wb2], w1 = sm[WATT + wb2 + 4];
                float wh0 = rna(w0), wl0 = w0 - wh0;
                float wh1 = rna(w1), wl1 = w1 - wh1;
                mma8(hr[nb], orh0, orh1, orh2, orh3, wh0, wh1);
                mma8(hr[nb], orl0, orl1, orl2, orl3, wh0, wh1);
                mma8(hr[nb], orh0, orh1, orh2, orh3, wl0, wl1);
                mma8(hi_[nb], oih0, oih1, oih2, oih3, wh0, wh1);
                mma8(hi_[nb], oil0, oil1, oil2, oil3, wh0, wh1);
                mma8(hi_[nb], oih0, oih1, oih2, oih3, wl0, wl1);
            }
        }

        float2* Ob = Og + ((size_t)b * N + qi0) * 64;
        #pragma unroll
        for (int nb = 0; nb < 4; ++nb)
            #pragma unroll
            for (int r = 0; r < 4; ++r) {
                int il = i0p + g + ((r & 2) ? 8 : 0);
                int fo = f0p + nb * 8 + 2 * t + (r & 1);
                float bb = sm[BIAS + fo];
                Ob[il * 64 + fo] = make_float2(hr[nb][r] + bb, hi_[nb][r] + bb);
            }
    }
}

extern "C" void kernel_launch(void* const* d_in, const int* in_sizes, int n_in,
                              void* d_out, int out_size)
{
    const float2* Q = (const float2*)d_in[0];
    const float2* K = (const float2*)d_in[1];
    const float2* V = (const float2*)d_in[2];
    const float*  W = (const float*)d_in[3];
    const float*  bb = (const float*)d_in[4];
    float2* O = (float2*)d_out;

    static bool attr_set = false;
    if (!attr_set) {
        cudaFuncSetAttribute(attn_k, cudaFuncAttributeMaxDynamicSharedMemorySize, SMB);
        attr_set = true;
    }

    attn_k<<<dim3(32, 4), NT, SMB>>>(Q, K, V, W, bb, O);
}